// round 14
// baseline (speedup 1.0000x reference)
#include <cuda_runtime.h>
#include <cuda_fp16.h>

#define BB 128
#define TT 512
#define CC 128

#define EBIAS 2.5f            // E' = exp(trans - EBIAS)
#define KSCALE 0.0212797f     // exp(-GROW), GROW = 3.85
#define MSTEP 6.35f           // EBIAS + GROW added to m each step
#define BOFF  6.0f            // backward init log-offset (fp16 overflow guard)

#define BARX(id) asm volatile("bar.sync %0, %1;" :: "r"(id), "r"(128) : "memory")

__device__ float g_partial[BB];

__device__ __forceinline__ float block_reduce_sum_256(float v, float* sh8) {
    #pragma unroll
    for (int o = 16; o > 0; o >>= 1)
        v += __shfl_xor_sync(0xffffffffu, v, o);
    int w = threadIdx.x >> 5;
    if ((threadIdx.x & 31) == 0) sh8[w] = v;
    __syncthreads();
    float r = ((sh8[0] + sh8[1]) + (sh8[2] + sh8[3]))
            + ((sh8[4] + sh8[5]) + (sh8[6] + sh8[7]));
    __syncthreads();
    return r;
}

// One chain step (forward or backward — layout-agnostic). ECOL is a register
// array NAME (keeps it register-resident). CUR is the compile-time ping-pong.
// Uses/updates: t, ps, m, ef0, ef1; reads h, L, niter, fb, j. One named barrier.
#define CRF_STEP(ECOL, CUR)                                                      \
    {                                                                            \
        float c = (t == 0) ? 1.0f : __half2float(ps[CUR][0]);                    \
        float ef_eff = (ef0 * KSCALE) * __fdividef(1.0f, c);                     \
        __half efh = __float2half_rn(ef_eff);                                    \
        int  rown = h ? (L - 4 - t) : (t + 2);                                   \
        bool valn = h ? (t + 2 <= niter - 2) : (t + 2 < niter);                  \
        int  rowc = rown < 0 ? 0 : rown;                                         \
        float ef2 = valn ? __expf(fb[(size_t)rowc * CC]) : 1.0f;                 \
        const uint4* pv = (const uint4*)ps[CUR];                                 \
        __half2 acc0 = __floats2half2_rn(0.f, 0.f), acc1 = acc0, acc2 = acc0,    \
                acc3 = acc0, acc4 = acc0, acc5 = acc0, acc6 = acc0, acc7 = acc0; \
        _Pragma("unroll")                                                        \
        for (int ii = 0; ii < 16; ii++) {                                        \
            uint4 q = pv[ii];                                                    \
            __half2 q0 = *reinterpret_cast<__half2*>(&q.x);                      \
            __half2 q1 = *reinterpret_cast<__half2*>(&q.y);                      \
            __half2 q2 = *reinterpret_cast<__half2*>(&q.z);                      \
            __half2 q3 = *reinterpret_cast<__half2*>(&q.w);                      \
            if ((ii & 1) == 0) {                                                 \
                acc0 = __hfma2(q0, ECOL[4 * ii + 0], acc0);                      \
                acc1 = __hfma2(q1, ECOL[4 * ii + 1], acc1);                      \
                acc2 = __hfma2(q2, ECOL[4 * ii + 2], acc2);                      \
                acc3 = __hfma2(q3, ECOL[4 * ii + 3], acc3);                      \
            } else {                                                             \
                acc4 = __hfma2(q0, ECOL[4 * ii + 0], acc4);                      \
                acc5 = __hfma2(q1, ECOL[4 * ii + 1], acc5);                      \
                acc6 = __hfma2(q2, ECOL[4 * ii + 2], acc6);                      \
                acc7 = __hfma2(q3, ECOL[4 * ii + 3], acc7);                      \
            }                                                                    \
        }                                                                        \
        __half2 t4a = __hadd2(acc0, acc1);                                       \
        __half2 t4b = __hadd2(acc2, acc3);                                       \
        __half2 t4c = __hadd2(acc4, acc5);                                       \
        __half2 t4d = __hadd2(acc6, acc7);                                       \
        __half2 s2  = __hadd2(__hadd2(t4a, t4b), __hadd2(t4c, t4d));             \
        __half  shh = __hadd(__low2half(s2), __high2half(s2));                   \
        ps[(CUR) ^ 1][j] = __hmul(shh, efh);                                     \
        m += MSTEP + __logf(c);                                                  \
        ef0 = ef1; ef1 = ef2;                                                    \
        BARX(1 + h);                                                             \
        t++;                                                                     \
    }

__global__ __launch_bounds__(256, 1)
void crf_forward_kernel(const float* __restrict__ feats,
                        const int*   __restrict__ mask,
                        const int*   __restrict__ tags,
                        const float* __restrict__ trans)
{
    const int b   = blockIdx.x;
    const int tid = threadIdx.x;
    const int j   = tid & 127;     // class index owned within group
    const int h   = tid >> 7;      // 0 = forward chain, 1 = backward chain

    __shared__ __align__(16) __half p_f[2][CC];   // scaled alpha
    __shared__ __align__(16) __half p_b[2][CC];   // scaled beta
    __shared__ float sh8[8];
    __shared__ float sh_m[2];

    // ---- sequence length (contiguous prefix mask) ----
    const int* mrow = mask + b * TT;
    int cnt = mrow[tid] + mrow[tid + 256];
    const int L  = (int)block_reduce_sum_256((float)cnt, sh8);
    const int tm = L >> 1;                    // fwd steps; bwd steps = L-tm >= 1
    const int niter = (h == 0) ? tm : (L - tm);

    // ---- E' in fp16 registers, two complementarily-rounded copies.
    // fwd thread: column j (i varies); bwd thread: row j (k varies).
    __half2 E2a[64], E2b[64];
    #pragma unroll
    for (int ii = 0; ii < 64; ii++) {
        int i0 = (h == 0) ? ((2 * ii + 0) * CC + j) : (j * CC + 2 * ii + 0);
        int i1 = (h == 0) ? ((2 * ii + 1) * CC + j) : (j * CC + 2 * ii + 1);
        float lo = __expf(trans[i0] - EBIAS);    // exp(-1e5) -> 0
        float hi = __expf(trans[i1] - EBIAS);
        __half hlo = __float2half_rn(lo), hhi = __float2half_rn(hi);
        E2a[ii] = __halves2half2(hlo, hhi);
        __half blo = __float2half_rn(2.0f * lo - __half2float(hlo));
        __half bhi = __float2half_rn(2.0f * hi - __half2float(hhi));
        E2b[ii] = __halves2half2(blo, bhi);
    }

    const float* fb = feats + (size_t)b * TT * CC + j;

    // ---- per-chain init (bookkeeping identical to validated R10) ----
    // fwd : alpha0 = onehot(START); iter t multiplies by ef row t (all t < tm)
    // bwd : q0 = ef_{L-1} (.) exp(trans[.,STOP]) * e^{-BOFF};
    //       iter t multiplies by ef row L-2-t for t <= niter-2; last iter bare.
    float m, ef0, ef1;
    __half (*ps)[CC] = (h == 0) ? p_f : p_b;
    if (h == 0) {
        p_f[0][j] = __float2half_rn((j == CC - 2) ? 1.0f : 0.0f);
        m = 0.0f;
        ef0 = (niter >= 1) ? __expf(fb[0])  : 1.0f;
        ef1 = (niter >= 2) ? __expf(fb[CC]) : 1.0f;
    } else {
        p_b[0][j] = __float2half_rn(
            __expf(fb[(size_t)(L - 1) * CC] + trans[j * CC + (CC - 1)] - BOFF));
        m = BOFF;
        ef0 = (niter >= 2) ? __expf(fb[(size_t)(L - 2) * CC]) : 1.0f;
        ef1 = (niter >= 3) ? __expf(fb[(size_t)(L - 3) * CC]) : 1.0f;
    }
    __syncthreads();

    // ---- hot loop: independent chains, one named barrier per step ----
    int t = 0;
    {
        int nP = niter >> 1;
        for (int p = 0; p < nP; p++) {
            CRF_STEP(E2a, 0);
            CRF_STEP(E2b, 1);
        }
    }
    int cur = 0;
    if (t < niter) {             // odd tail step
        CRF_STEP(E2a, 0);
        cur = 1;
    }
    if (j == 0) sh_m[h] = m;
    __syncthreads();

    // ---- meet in the middle: logZ = m_f + m_b + log( alpha~_tm . beta~_tm ) ----
    const int curf = tm & 1;
    const int curb = (L - tm) & 1;
    float contrib = (h == 0)
        ? __half2float(p_f[curf][j]) * __half2float(p_b[curb][j]) : 0.0f;
    float dot = block_reduce_sum_256(contrib, sh8);
    float logZ = sh_m[0] + sh_m[1] + __logf(dot);

    // ---- gold path score (fp32 exact) ----
    const int* tg = tags + b * TT;
    const float* fbase = feats + (size_t)b * TT * CC;
    float sc = 0.0f;
    for (int tt = tid; tt < L; tt += 256)
        sc += fbase[(size_t)tt * CC + tg[tt]];
    for (int k = tid; k <= L; k += 256) {
        int prev = (k == 0) ? (CC - 2) : tg[k - 1];
        int curt = (k == L) ? (CC - 1) : tg[k];
        sc += trans[prev * CC + curt];
    }
    float tots = block_reduce_sum_256(sc, sh8);

    if (tid == 0) g_partial[b] = logZ - tots;
}

__global__ void crf_finalize_kernel(float* __restrict__ out)
{
    __shared__ float s[BB];
    int tid = threadIdx.x;
    s[tid] = g_partial[tid];
    __syncthreads();
    #pragma unroll
    for (int off = 64; off > 0; off >>= 1) {
        if (tid < off) s[tid] += s[tid + off];
        __syncthreads();
    }
    if (tid == 0) out[0] = s[0] / (float)BB;
}

extern "C" void kernel_launch(void* const* d_in, const int* in_sizes, int n_in,
                              void* d_out, int out_size)
{
    const float* feats = (const float*)d_in[0];
    const int*   mask  = (const int*)  d_in[1];
    const int*   tags  = (const int*)  d_in[2];
    const float* trans = (const float*)d_in[3];
    float* out = (float*)d_out;

    crf_forward_kernel<<<BB, 256>>>(feats, mask, tags, trans);
    crf_finalize_kernel<<<1, BB>>>(out);
}

// round 15
// speedup vs baseline: 1.4712x; 1.4712x over previous
#include <cuda_runtime.h>
#include <cuda_fp16.h>

#define BB 128
#define TT 512
#define CC 128

#define EBIAS 2.5f            // E' = exp(trans - EBIAS)
#define KSCALE 0.0212797f     // exp(-GROW), GROW = 3.85
#define MSTEP 6.35f           // EBIAS + GROW added to m each step

__device__ float g_partial[BB];

__device__ __forceinline__ float block_reduce_sum_256(float v, float* sh8) {
    #pragma unroll
    for (int o = 16; o > 0; o >>= 1)
        v += __shfl_xor_sync(0xffffffffu, v, o);
    int w = threadIdx.x >> 5;
    if ((threadIdx.x & 31) == 0) sh8[w] = v;
    __syncthreads();
    float r = ((sh8[0] + sh8[1]) + (sh8[2] + sh8[3]))
            + ((sh8[4] + sh8[5]) + (sh8[6] + sh8[7]));
    __syncthreads();
    return r;
}

// One forward step. ECOL is a register-array NAME (stays register-resident).
// Thread (j, h): half-matvec over i in [h*64, h*64+64). Cross-half combine is
// ALL-fp16 via shfl of the packed half2 — no F2F on the critical path.
#define CRF_STEP(ECOL, CUR, t)                                                   \
    {                                                                            \
        /* step-top: overlapped with matvec (independent of this step's accs) */\
        float c = ((t) == 0) ? 1.0f : __half2float(p_s[CUR][0]);                 \
        float ef_eff = (ef0 * KSCALE) * __fdividef(1.0f, c);                     \
        __half efh = __float2half_rn(ef_eff);                                    \
        float ef2 = ((t) + 2 < L) ? __expf(fb[(size_t)((t) + 2) * CC]) : 1.0f;   \
        const uint4* pv = (const uint4*)(p_s[CUR] + (h << 6));                   \
        __half2 acc0 = __floats2half2_rn(0.f, 0.f), acc1 = acc0, acc2 = acc0,    \
                acc3 = acc0, acc4 = acc0, acc5 = acc0, acc6 = acc0, acc7 = acc0; \
        _Pragma("unroll")                                                        \
        for (int ii = 0; ii < 8; ii++) {                                         \
            uint4 q = pv[ii];                                                    \
            __half2 q0 = *reinterpret_cast<__half2*>(&q.x);                      \
            __half2 q1 = *reinterpret_cast<__half2*>(&q.y);                      \
            __half2 q2 = *reinterpret_cast<__half2*>(&q.z);                      \
            __half2 q3 = *reinterpret_cast<__half2*>(&q.w);                      \
            if ((ii & 1) == 0) {                                                 \
                acc0 = __hfma2(q0, ECOL[4 * ii + 0], acc0);                      \
                acc1 = __hfma2(q1, ECOL[4 * ii + 1], acc1);                      \
                acc2 = __hfma2(q2, ECOL[4 * ii + 2], acc2);                      \
                acc3 = __hfma2(q3, ECOL[4 * ii + 3], acc3);                      \
            } else {                                                             \
                acc4 = __hfma2(q0, ECOL[4 * ii + 0], acc4);                      \
                acc5 = __hfma2(q1, ECOL[4 * ii + 1], acc5);                      \
                acc6 = __hfma2(q2, ECOL[4 * ii + 2], acc6);                      \
                acc7 = __hfma2(q3, ECOL[4 * ii + 3], acc7);                      \
            }                                                                    \
        }                                                                        \
        __half2 t4a = __hadd2(acc0, acc1);                                       \
        __half2 t4b = __hadd2(acc2, acc3);                                       \
        __half2 t4c = __hadd2(acc4, acc5);                                       \
        __half2 t4d = __hadd2(acc6, acc7);                                       \
        __half2 s2  = __hadd2(__hadd2(t4a, t4b), __hadd2(t4c, t4d));             \
        /* cross-half combine in packed fp16: shfl the half2 as u32 */           \
        unsigned sv = *reinterpret_cast<unsigned*>(&s2);                         \
        unsigned ov = __shfl_xor_sync(0xffffffffu, sv, 16);                      \
        __half2 s2f = __hadd2(s2, *reinterpret_cast<__half2*>(&ov));             \
        __half  shh = __hadd(__low2half(s2f), __high2half(s2f));                 \
        if (h == 0) p_s[(CUR) ^ 1][j] = __hmul(shh, efh);                        \
        m += MSTEP + __logf(c);                                                  \
        ef0 = ef1; ef1 = ef2;                                                    \
        __syncthreads();                                                         \
    }

__global__ __launch_bounds__(256, 1)
void crf_forward_kernel(const float* __restrict__ feats,
                        const int*   __restrict__ mask,
                        const int*   __restrict__ tags,
                        const float* __restrict__ trans)
{
    const int b   = blockIdx.x;
    const int tid = threadIdx.x;
    const int w   = tid >> 5;
    const int l   = tid & 31;
    const int j   = (w << 4) | (l & 15);   // class column owned
    const int h   = l >> 4;                // i-half (sibling lane is l ^ 16)

    __shared__ __align__(16) __half p_s[2][CC];
    __shared__ float sh8[8];

    // ---- sequence length (contiguous prefix mask) ----
    const int* mrow = mask + b * TT;
    int cnt = mrow[tid] + mrow[tid + 256];
    const int L = (int)block_reduce_sum_256((float)cnt, sh8);

    // ---- E half-column in fp16, two complementarily-rounded copies ----
    __half2 E2a[32], E2b[32];
    #pragma unroll
    for (int ii = 0; ii < 32; ii++) {
        int i0 = (h << 6) + 2 * ii;
        float lo = __expf(trans[(i0 + 0) * CC + j] - EBIAS);  // exp(-1e5)->0
        float hi = __expf(trans[(i0 + 1) * CC + j] - EBIAS);
        __half hlo = __float2half_rn(lo), hhi = __float2half_rn(hi);
        E2a[ii] = __halves2half2(hlo, hhi);
        __half blo = __float2half_rn(2.0f * lo - __half2float(hlo));
        __half bhi = __float2half_rn(2.0f * hi - __half2float(hhi));
        E2b[ii] = __halves2half2(blo, bhi);
    }

    // ---- init: p = one-hot(START) ----
    if (h == 0) p_s[0][j] = __float2half_rn((j == CC - 2) ? 1.0f : 0.0f);
    __syncthreads();

    const float* fb = feats + (size_t)b * TT * CC + j;
    float m   = 0.0f;
    float ef0 = __expf(fb[0]);                        // L >= 1 always
    float ef1 = (L > 1) ? __expf(fb[CC]) : 1.0f;

    // ---- forward scan: 2 steps per trip, ping-pong unrolled ----
    int t = 0;
    int nPairs = L >> 1;
    for (int p = 0; p < nPairs; p++) {
        CRF_STEP(E2a, 0, t); t++;
        CRF_STEP(E2b, 1, t); t++;
    }
    int cur = 0;
    if (t < L) {                 // odd tail step
        CRF_STEP(E2a, 0, t); t++;
        cur = 1;
    }

    // ---- logZ = m + log( sum_j p[j] * exp(trans[j][STOP]) ) ----
    float contrib = (h == 0)
        ? __half2float(p_s[cur][j]) * __expf(trans[j * CC + (CC - 1)]) : 0.0f;
    float tot = block_reduce_sum_256(contrib, sh8);
    float logZ = m + __logf(tot);

    // ---- gold path score (fp32 exact) ----
    const int* tg = tags + b * TT;
    const float* fbase = feats + (size_t)b * TT * CC;
    float sc = 0.0f;
    for (int tt = tid; tt < L; tt += 256)
        sc += fbase[(size_t)tt * CC + tg[tt]];
    for (int k = tid; k <= L; k += 256) {
        int prev = (k == 0) ? (CC - 2) : tg[k - 1];
        int curt = (k == L) ? (CC - 1) : tg[k];
        sc += trans[prev * CC + curt];
    }
    float tots = block_reduce_sum_256(sc, sh8);

    if (tid == 0) g_partial[b] = logZ - tots;
}

__global__ void crf_finalize_kernel(float* __restrict__ out)
{
    __shared__ float s[BB];
    int tid = threadIdx.x;
    s[tid] = g_partial[tid];
    __syncthreads();
    #pragma unroll
    for (int off = 64; off > 0; off >>= 1) {
        if (tid < off) s[tid] += s[tid + off];
        __syncthreads();
    }
    if (tid == 0) out[0] = s[0] / (float)BB;
}

extern "C" void kernel_launch(void* const* d_in, const int* in_sizes, int n_in,
                              void* d_out, int out_size)
{
    const float* feats = (const float*)d_in[0];
    const int*   mask  = (const int*)  d_in[1];
    const int*   tags  = (const int*)  d_in[2];
    const float* trans = (const float*)d_in[3];
    float* out = (float*)d_out;

    crf_forward_kernel<<<BB, 256>>>(feats, mask, tags, trans);
    crf_finalize_kernel<<<1, BB>>>(out);
}